// round 13
// baseline (speedup 1.0000x reference)
#include <cuda_runtime.h>
#include <cuda_bf16.h>

#define N 8192
#define ROWLEN 85
#define NCLS 80
#define CAP 256
#define MW 8               // CAP/32 suppression-mask words
#define FT 1024            // threads per block
#define NBLK 144           // 80 NMS + 64 rank; single wave, 1 block/SM
#define RB 64              // rank blocks (ids 80..143)
#define SCANB 32           // first 32 rank blocks scan 512 bins each
#define BINS 16384         // bin = (key>>16) - 0xC080  (scores in [0,1))
#define ROWS_PER_RB (N / RB)   // 128
#define PFE 5              // prefetched output elements per thread

__device__ unsigned g_skey[N];          // ~float_bits(score); asc == score desc
__device__ unsigned g_pack[N];          // row<<7 | cat
__device__ unsigned g_hist[BINS];       // bin counts (reset in P3)
__device__ unsigned g_cnt2[BINS];       // scatter cursors (reset in P3)
__device__ unsigned g_prefix[BINS];     // exclusive bin prefix
__device__ unsigned g_chunkTot[SCANB];  // per-chunk totals
__device__ unsigned g_bkey[N];          // bucketed keys
__device__ int g_brow[N];               // bucketed rows
__device__ int g_rank[N];               // row -> global sorted position
__device__ float g_keepf[N];            // keep flag by original row
__device__ unsigned long long g_tick;   // monotone ticket counter (epochs)
__device__ unsigned long long g_c1;     // P1 done (144)
__device__ unsigned long long g_r1, g_r2, g_r3;   // rank-internal (64)
__device__ unsigned long long g_c2;     // P2 done (144)

struct NmsShared {
    unsigned long long keys[CAP];    // compacted (unsorted)
    unsigned long long skeys[CAP];   // counting-sorted
    float4 box[CAP];
    float area[CAP];
    unsigned mask[(CAP + 1) * MW];   // +1 row: merge prefetch overshoot
    unsigned sup[MW];
    int cnt;
};

// arrive + spin barrier on a monotone counter (replay-safe: epoch-scaled
// targets). EVERY thread fences before syncthreads so all block writes are
// released before the flag arrive.
__device__ __forceinline__ void gsync(unsigned long long* c, unsigned long long tgt) {
    __threadfence();
    __syncthreads();
    if (threadIdx.x == 0) {
        atomicAdd(c, 1ull);
        while (*(volatile unsigned long long*)c < tgt) {}
        __threadfence();
    }
    __syncthreads();
}

__global__ void __launch_bounds__(FT, 1)
yolonms_kernel(const float* __restrict__ X, float* __restrict__ out) {
    extern __shared__ __align__(16) char sm[];
    __shared__ unsigned long long s_ep;
    __shared__ unsigned s_ws[32];

    int t = threadIdx.x, b = blockIdx.x;
    int lane = t & 31, w = t >> 5;

    if (t == 0) s_ep = atomicAdd(&g_tick, 1ull) / NBLK;
    __syncthreads();
    unsigned long long ep = s_ep;

    // ---------------- Phase 1: score + histogram (all blocks) ----------------
    for (int r = b * 32 + w; r < N; r += NBLK * 32) {
        const float* row = X + (long)r * ROWLEN;
        float v0 = row[5 + lane];
        float v1 = row[37 + lane];
        float v2 = (lane < 16) ? row[69 + lane] : -1.0f;
        float best = v0; int bi = lane;
        if (v1 > best) { best = v1; bi = lane + 32; }
        if (v2 > best) { best = v2; bi = lane + 64; }

        unsigned bb = __float_as_uint(best);            // nonneg -> monotone
        unsigned vmax = __reduce_max_sync(0xffffffffu, bb);
        int cand = (bb == vmax) ? bi : 0x7fffffff;      // smallest idx wins ties
        int bimin = __reduce_min_sync(0xffffffffu, cand);
        if (lane == 0) {
            float score = row[4] * __uint_as_float(vmax);   // in [0, 1)
            unsigned key = ~__float_as_uint(score);
            g_skey[r] = key;
            g_pack[r] = ((unsigned)r << 7) | (unsigned)bimin;
            unsigned bin = (key >> 16) - 0xC080u;
            if (bin >= BINS) bin = BINS - 1;
            atomicAdd(&g_hist[bin], 1u);
        }
    }
    gsync(&g_c1, (ep + 1) * NBLK);

    // ---------------- Phase 2: NMS blocks || rank blocks ----------------
    if (b < NCLS) {
        // per-class greedy NMS. Class offsets in the reference make cross-
        // class IoU exactly 0, so suppression decomposes per class.
        NmsShared& S = *reinterpret_cast<NmsShared*>(sm);
        unsigned c = b;

        if (t == 0) S.cnt = 0;
        __syncthreads();

        // front-load pack+key values: independent loads (one MLP burst),
        // then the atomic compaction loop runs from registers.
        unsigned pk[N / FT], sk[N / FT];
        #pragma unroll
        for (int q = 0; q < N / FT; q++) {
            pk[q] = g_pack[q * FT + t];
            sk[q] = g_skey[q * FT + t];
        }
        #pragma unroll
        for (int q = 0; q < N / FT; q++) {
            if ((pk[q] & 127u) == c) {
                int slot = atomicAdd(&S.cnt, 1);
                if (slot < CAP)
                    S.keys[slot] = ((unsigned long long)sk[q] << 32) | pk[q];
            }
        }
        __syncthreads();
        int m = min(S.cnt, CAP);

        // counting sort: keys unique (row embedded) -> exact permutation.
        // asc key == score desc, ties by ascending row (== stable argsort).
        if (t < m) {
            unsigned long long k = S.keys[t];
            int r = 0;
            for (int j = 0; j < m; j++) r += (S.keys[j] < k);
            S.skeys[r] = k;
        }
        __syncthreads();

        if (t < m) {
            int idx = (int)(((unsigned)(S.skeys[t] & 0xFFFFFFFFull)) >> 7);
            const float* row = X + (long)idx * ROWLEN;
            float x1 = row[0], y1 = row[1], x2 = row[2], y2 = row[3];
            S.box[t] = make_float4(x1, y1, x2, y2);
            S.area[t] = (x2 - x1) * (y2 - y1);
        }
        for (int p = t; p < (m + 1) * MW; p += FT) S.mask[p] = 0u;
        __syncthreads();

        // mask[i] = { j > i : IoU(i,j) > 0.5 } — fully parallel over 32 warps
        for (int i = w; i < m; i += FT / 32) {
            float4 bi = S.box[i];
            float ai = S.area[i];
            for (int j = i + 1 + lane; j < m; j += 32) {
                float4 bj = S.box[j];
                float xx1 = fmaxf(bi.x, bj.x);
                float yy1 = fmaxf(bi.y, bj.y);
                float xx2 = fminf(bi.z, bj.z);
                float yy2 = fminf(bi.w, bj.w);
                float ww = fmaxf(xx2 - xx1, 0.0f);
                float hh = fmaxf(yy2 - yy1, 0.0f);
                float inter = ww * hh;
                float iou = inter / (ai + S.area[j] - inter);
                if (iou > 0.5f) atomicOr(&S.mask[i * MW + (j >> 5)], 1u << (j & 31));
            }
        }
        __syncthreads();

        // serial greedy bit-merge, single thread, unconditional prefetch:
        // loads never depend on sup state -> dependent chain is select+OR only.
        if (t == 0) {
            unsigned sx[MW];
            #pragma unroll
            for (int q = 0; q < MW; q++) sx[q] = 0u;
            unsigned pm[MW];
            #pragma unroll
            for (int q = 0; q < MW; q++) pm[q] = S.mask[q];
            for (int i = 0; i < m; i++) {
                unsigned nm[MW];
                #pragma unroll
                for (int q = 0; q < MW; q++) nm[q] = S.mask[(i + 1) * MW + q];
                unsigned kept = ((sx[i >> 5] >> (i & 31)) & 1u) ^ 1u;
                unsigned sel = 0u - kept;          // all-ones if kept
                #pragma unroll
                for (int q = 0; q < MW; q++) sx[q] |= (pm[q] & sel);
                #pragma unroll
                for (int q = 0; q < MW; q++) pm[q] = nm[q];
            }
            #pragma unroll
            for (int q = 0; q < MW; q++) S.sup[q] = sx[q];
        }
        __syncthreads();

        if (t < m) {
            int idx = (int)(((unsigned)(S.skeys[t] & 0xFFFFFFFFull)) >> 7);
            g_keepf[idx] = ((S.sup[t >> 5] >> (t & 31)) & 1u) ? 0.0f : 1.0f;
        }
    } else {
        // ---- rank blocks (80..143): counting-sort rank over 16K bins ----
        int rb = b - NCLS;

        // step A: 32 scan blocks, 512 bins each, warp-shuffle scan
        unsigned v = 0, incl = 0;
        if (rb < SCANB && t < 512) {
            int bin = rb * 512 + t;
            v = g_hist[bin];
            incl = v;
            #pragma unroll
            for (int off = 1; off < 32; off <<= 1) {
                unsigned u = __shfl_up_sync(0xffffffffu, incl, off);
                if (lane >= off) incl += u;
            }
            if (lane == 31) s_ws[w] = incl;     // 16 warp sums
        }
        __syncthreads();
        if (rb < SCANB && t < 32) {
            unsigned x = (lane < 16) ? s_ws[lane] : 0u;
            #pragma unroll
            for (int off = 1; off < 32; off <<= 1) {
                unsigned u = __shfl_up_sync(0xffffffffu, x, off);
                if (lane >= off) x += u;
            }
            if (lane < 16) s_ws[lane] = x;       // inclusive warp-sum scan
            if (lane == 15) g_chunkTot[rb] = x;
        }
        __syncthreads();
        unsigned excl_chunk = 0;
        if (rb < SCANB && t < 512) {
            unsigned wbase = (w > 0) ? s_ws[w - 1] : 0u;
            excl_chunk = wbase + incl - v;       // exclusive within chunk
        }
        gsync(&g_r1, (ep + 1) * RB);

        // step B: add chunk bases, publish global prefix
        if (rb < SCANB && t < 512) {
            unsigned basesum = 0;
            #pragma unroll
            for (int cc = 0; cc < SCANB; cc++) {
                unsigned cv = g_chunkTot[cc];
                if (cc < rb) basesum += cv;
            }
            g_prefix[rb * 512 + t] = basesum + excl_chunk;
        }
        gsync(&g_r2, (ep + 1) * RB);

        // step C: bucket scatter (128 rows per rank block)
        if (t < ROWS_PER_RB) {
            int r = rb * ROWS_PER_RB + t;
            unsigned key = g_skey[r];
            unsigned bin = (key >> 16) - 0xC080u;
            if (bin >= BINS) bin = BINS - 1;
            unsigned slot = g_prefix[bin] + atomicAdd(&g_cnt2[bin], 1u);
            g_bkey[slot] = key;
            g_brow[slot] = r;
        }
        gsync(&g_r3, (ep + 1) * RB);

        // step D: within-bucket exact rank by (key asc, row asc)
        if (t < ROWS_PER_RB) {
            int s = rb * ROWS_PER_RB + t;
            unsigned key = g_bkey[s];
            int row = g_brow[s];
            unsigned bin = (key >> 16) - 0xC080u;
            if (bin >= BINS) bin = BINS - 1;
            unsigned start = g_prefix[bin];
            unsigned len = g_hist[bin];
            int cnt = 0;
            for (unsigned i = start; i < start + len; i++) {
                unsigned k2 = g_bkey[i];
                if (k2 < key || (k2 == key && g_brow[i] < row)) cnt++;
            }
            g_rank[row] = (int)start + cnt;
        }
    }

    // ---- prefetch P3's X values BEFORE the barrier: X is read-only input,
    // so these loads are safe to issue early; their latency hides behind the
    // barrier wait. (g_rank/g_keepf are NOT touched here — they are mutable
    // and must be read with plain loads strictly after the barrier.)
    const int total = N * ROWLEN;
    float xv[PFE];
    #pragma unroll
    for (int k = 0; k < PFE; k++) {
        int e = b * FT + t + k * NBLK * FT;
        xv[k] = (e < total) ? X[e] : 0.0f;
    }

    gsync(&g_c2, (ep + 1) * NBLK);

    // ---------------- Phase 3: output scatter + reset for next epoch ----------------
    // Plain loads only (no __ldg): g_rank/g_keepf were written this kernel by
    // other blocks; ld.global.nc would license the compiler to hoist them
    // across the barrier (it assumes .nc data is immutable).
    {
        int i = b * FT + t;
        if (i < BINS) { g_hist[i] = 0u; g_cnt2[i] = 0u; }
    }
    #pragma unroll
    for (int k = 0; k < PFE; k++) {
        int e = b * FT + t + k * NBLK * FT;
        if (e < total) {
            int row = e / ROWLEN;
            int col = e - row * ROWLEN;
            int rk = g_rank[row];
            float kf = g_keepf[row];
            out[(long)rk * ROWLEN + col] = xv[k] * kf;
        }
    }
}

// ---------------------------------------------------------------------------
extern "C" void kernel_launch(void* const* d_in, const int* in_sizes, int n_in,
                              void* d_out, int out_size) {
    const float* X = (const float*)d_in[0];
    float* out = (float*)d_out;

    int smem = (int)sizeof(NmsShared);
    static int smem_set = 0;
    if (!smem_set) {
        cudaFuncSetAttribute(yolonms_kernel,
                             cudaFuncAttributeMaxDynamicSharedMemorySize, smem);
        smem_set = 1;
    }

    yolonms_kernel<<<NBLK, FT, smem>>>(X, out);
}